// round 1
// baseline (speedup 1.0000x reference)
#include <cuda_runtime.h>
#include <cuda_bf16.h>

// KANConv2d fused kernel, fp32 CUDA-core baseline.
// out[N=16384, OC=128] = A[N, 5184] @ Wc[5184, 128]
//   A(n, d*9+0)   = silu(x_patch(n,d))
//   A(n, d*9+1+k) = Bspline_k(x_patch(n,d)),  k=0..7 (cubic, uniform grid)
//   Wc(d*9+0, o)  = base_weight[o,d]
//   Wc(d*9+1+k,o) = spline_weight[o,d,k] * spline_scaler[o,d]

#define OC      128
#define D_TOT   576     // 64 * 3 * 3
#define NBAS    8
#define KPD     9       // activation channels per patch feature
#define DCHUNK  4
#define KKCHUNK (DCHUNK * KPD)   // 36
#define TPOS    128              // spatial positions per block
#define THREADS 256
#define HW      64
#define L_IMG   (HW * HW)        // 4096

__device__ float g_Wc[D_TOT * KPD * OC];   // (d, kc, o) — 2.65 MB scratch

__global__ void combine_w_kernel(const float* __restrict__ bw,
                                 const float* __restrict__ sw,
                                 const float* __restrict__ ss) {
    int idx = blockIdx.x * blockDim.x + threadIdx.x;
    if (idx >= D_TOT * KPD * OC) return;
    int o  = idx % OC;
    int t  = idx / OC;
    int kc = t % KPD;
    int d  = t / KPD;
    float v;
    if (kc == 0) {
        v = bw[o * D_TOT + d];
    } else {
        v = sw[(o * D_TOT + d) * NBAS + (kc - 1)] * ss[o * D_TOT + d];
    }
    g_Wc[idx] = v;
}

__device__ __forceinline__ void compute_acts(float v, float* out9) {
    // silu
    out9[0] = v / (1.0f + __expf(-v));
    // grid t[j] = (j-3)*0.4 - 1, j = 0..11  (matches reference fp32 construction)
    float t[12];
#pragma unroll
    for (int j = 0; j < 12; ++j) t[j] = (float)(j - 3) * 0.4f - 1.0f;
    float b[11];
#pragma unroll
    for (int j = 0; j < 11; ++j) b[j] = (v >= t[j] && v < t[j + 1]) ? 1.0f : 0.0f;
#pragma unroll
    for (int k = 1; k <= 3; ++k) {
#pragma unroll
        for (int j = 0; j < 11; ++j) {
            if (j + k < 11) {
                float left  = (v - t[j]) / (t[j + k] - t[j]);
                float right = (t[j + k + 1] - v) / (t[j + k + 1] - t[j + 1]);
                b[j] = left * b[j] + right * b[j + 1];   // reads old b[j+1] (not yet updated)
            }
        }
    }
#pragma unroll
    for (int k = 0; k < NBAS; ++k) out9[1 + k] = b[k];
}

__global__ __launch_bounds__(THREADS, 1)
void kan_main_kernel(const float* __restrict__ x, float* __restrict__ out) {
    __shared__ float sA[KKCHUNK][TPOS];
    __shared__ float sW[KKCHUNK][OC];

    const int bi  = blockIdx.x >> 5;    // image 0..3
    const int ti  = blockIdx.x & 31;    // spatial tile (128 positions = 2 image rows)
    const int tid = threadIdx.x;
    const int typ = tid & 15;           // position group: pos = typ*8 .. typ*8+7
    const int txo = tid >> 4;           // out-channel group: o = txo*8 .. txo*8+7

    const float* xb   = x + (size_t)bi * 64 * L_IMG;
    float*       outb = out + (size_t)bi * OC * L_IMG;
    const int s_base = ti * TPOS;

    float acc[8][8];
#pragma unroll
    for (int i = 0; i < 8; ++i)
#pragma unroll
        for (int j = 0; j < 8; ++j) acc[i][j] = 0.0f;

    for (int d0 = 0; d0 < D_TOT; d0 += DCHUNK) {
        __syncthreads();   // previous compute phase done reading sA/sW

        // ---- stage activations: DCHUNK*128 = 512 (d,pos) pairs, 2 per thread ----
#pragma unroll
        for (int it = 0; it < (DCHUNK * TPOS) / THREADS; ++it) {
            int pair = tid + it * THREADS;
            int dl = pair >> 7;        // 0..DCHUNK-1
            int p  = pair & 127;
            int d  = d0 + dl;
            int c  = d / 9;
            int r  = d - c * 9;
            int kh = r / 3;
            int kw = r - kh * 3;
            int s  = s_base + p;
            int ho = s >> 6, wo = s & 63;
            int h = ho + kh - 1;
            int w = wo + kw - 1;
            float v = 0.0f;
            if ((unsigned)h < (unsigned)HW && (unsigned)w < (unsigned)HW)
                v = xb[(c * HW + h) * HW + w];
            float a9[9];
            compute_acts(v, a9);
#pragma unroll
            for (int k = 0; k < 9; ++k) sA[dl * 9 + k][p] = a9[k];
        }

        // ---- stage weights: 36*128 = 4608 floats, 18 per thread, coalesced ----
        {
            const float* wsrc = g_Wc + (size_t)d0 * KPD * OC;
            float* wdst = &sW[0][0];
#pragma unroll
            for (int it = 0; it < (KKCHUNK * OC) / THREADS; ++it) {
                int idx = tid + it * THREADS;
                wdst[idx] = wsrc[idx];
            }
        }
        __syncthreads();

        // ---- compute: 36 K-slices, 8x8 register tile per thread ----
#pragma unroll 3
        for (int kk = 0; kk < KKCHUNK; ++kk) {
            float4 a0 = *(const float4*)&sA[kk][typ * 8];
            float4 a1 = *(const float4*)&sA[kk][typ * 8 + 4];
            float4 w0 = *(const float4*)&sW[kk][txo * 8];
            float4 w1 = *(const float4*)&sW[kk][txo * 8 + 4];
            float a[8] = {a0.x, a0.y, a0.z, a0.w, a1.x, a1.y, a1.z, a1.w};
            float wv[8] = {w0.x, w0.y, w0.z, w0.w, w1.x, w1.y, w1.z, w1.w};
#pragma unroll
            for (int i = 0; i < 8; ++i)
#pragma unroll
                for (int j = 0; j < 8; ++j)
                    acc[i][j] = fmaf(a[i], wv[j], acc[i][j]);
        }
    }

    // ---- write out: out[(bi*OC + o)*4096 + s], contiguous 8 positions/thread ----
#pragma unroll
    for (int j = 0; j < 8; ++j) {
        int o = txo * 8 + j;
        float* orow = outb + (size_t)o * L_IMG + s_base + typ * 8;
        float4 v0 = make_float4(acc[0][j], acc[1][j], acc[2][j], acc[3][j]);
        float4 v1 = make_float4(acc[4][j], acc[5][j], acc[6][j], acc[7][j]);
        *(float4*)(orow)     = v0;
        *(float4*)(orow + 4) = v1;
    }
}

extern "C" void kernel_launch(void* const* d_in, const int* in_sizes, int n_in,
                              void* d_out, int out_size) {
    const float* x  = (const float*)d_in[0];
    const float* bw = (const float*)d_in[1];
    const float* sw = (const float*)d_in[2];
    const float* ss = (const float*)d_in[3];
    float* out = (float*)d_out;

    int wtot = D_TOT * KPD * OC;
    combine_w_kernel<<<(wtot + 255) / 256, 256>>>(bw, sw, ss);
    kan_main_kernel<<<128, THREADS>>>(x, out);
}

// round 6
// speedup vs baseline: 4.1700x; 4.1700x over previous
#include <cuda_runtime.h>
#include <cuda_fp16.h>
#include <cstdint>

// ============================================================================
// KANConv2d: out[16384,128] = A[16384,5184] @ Wc[5184,128]
//   A(n, d*9+0)   = silu(x_patch(n,d))
//   A(n, d*9+1+k) = cubic B-spline basis k of x_patch(n,d), k=0..7
//   Wc(d*9+0, o)  = base_weight[o,d]
//   Wc(d*9+1+k,o) = spline_weight[o,d,k] * spline_scaler[o,d]
// Pipeline: (1) activations -> g_A fp16, (2) weights -> g_Wb fp16,
//           (3) mma.sync (HMMA) f16 GEMM, fp32 accumulators.
// NOTE: toolchain targets plain sm_103 (no 'a') -> tcgen05 unavailable;
//       mma.sync/ldmatrix/cp.async are the valid tensor-core path.
// ============================================================================

#define OC      128
#define D_TOT   576
#define NBAS    8
#define NK      5184          // 576 * 9
#define KC      64            // K halves per GEMM chunk (128 B rows, SW128)
#define NCHUNK  81            // 5184 / 64
#define NROWS   16384
#define HW      64
#define L_IMG   4096

__device__ __half g_A[(size_t)NROWS * NK];    // ~170 MB scratch
__device__ __half g_Wb[(size_t)OC * NK];      // 1.3 MB

// ---------------------------------------------------------------------------
// PTX helpers
// ---------------------------------------------------------------------------
__device__ __forceinline__ uint32_t smem_u32(const void* p) {
    uint32_t a;
    asm("{ .reg .u64 t; cvta.to.shared.u64 t, %1; cvt.u32.u64 %0, t; }"
        : "=r"(a) : "l"(p));
    return a;
}
#define CP_ASYNC16(sa, gp) \
    asm volatile("cp.async.cg.shared.global [%0], [%1], 16;" \
        :: "r"((uint32_t)(sa)), "l"(gp) : "memory")
#define CP_COMMIT() asm volatile("cp.async.commit_group;" ::: "memory")
#define CP_WAIT0()  asm volatile("cp.async.wait_group 0;" ::: "memory")

#define SW128(off) ((off) ^ (((off) >> 3) & 0x70))

__device__ __forceinline__ void ldsm_x4(uint32_t r[4], uint32_t addr) {
    asm volatile("ldmatrix.sync.aligned.m8n8.x4.shared.b16 {%0,%1,%2,%3}, [%4];"
                 : "=r"(r[0]), "=r"(r[1]), "=r"(r[2]), "=r"(r[3]) : "r"(addr));
}
__device__ __forceinline__ void mma16816(float c[4], const uint32_t a[4],
                                         uint32_t b0, uint32_t b1) {
    asm volatile(
        "mma.sync.aligned.m16n8k16.row.col.f32.f16.f16.f32 "
        "{%0,%1,%2,%3}, {%4,%5,%6,%7}, {%8,%9}, {%0,%1,%2,%3};"
        : "+f"(c[0]), "+f"(c[1]), "+f"(c[2]), "+f"(c[3])
        : "r"(a[0]), "r"(a[1]), "r"(a[2]), "r"(a[3]), "r"(b0), "r"(b1));
}

// ---------------------------------------------------------------------------
// Activation math (validated in round 1: rel_err 9.6e-7 in fp32)
// ---------------------------------------------------------------------------
__device__ __forceinline__ void compute_acts(float v, float* out9) {
    out9[0] = v / (1.0f + __expf(-v));
    float t[12];
#pragma unroll
    for (int j = 0; j < 12; ++j) t[j] = (float)(j - 3) * 0.4f - 1.0f;
    float b[11];
#pragma unroll
    for (int j = 0; j < 11; ++j) b[j] = (v >= t[j] && v < t[j + 1]) ? 1.0f : 0.0f;
#pragma unroll
    for (int k = 1; k <= 3; ++k) {
#pragma unroll
        for (int j = 0; j < 11; ++j) {
            if (j + k < 11) {
                float left  = (v - t[j]) / (t[j + k] - t[j]);
                float right = (t[j + k + 1] - v) / (t[j + k + 1] - t[j + 1]);
                b[j] = left * b[j] + right * b[j + 1];
            }
        }
    }
#pragma unroll
    for (int k = 0; k < NBAS; ++k) out9[1 + k] = b[k];
}

// ---------------------------------------------------------------------------
// Kernel 1: activations -> g_A[n][k] fp16   (block: 16 rows x full K)
// ---------------------------------------------------------------------------
#define ACT_TN 16
#define ACT_DC 64
__global__ __launch_bounds__(256)
void kan_act_kernel(const float* __restrict__ x) {
    __shared__ __half sT[ACT_TN][584];
    const int tid = threadIdx.x;
    const int n0 = blockIdx.x * ACT_TN;

    for (int d0 = 0; d0 < D_TOT; d0 += ACT_DC) {
#pragma unroll
        for (int it = 0; it < (ACT_TN * ACT_DC) / 256; ++it) {
            int item = tid + it * 256;
            int nl = item & (ACT_TN - 1);
            int dl = item / ACT_TN;
            int d  = d0 + dl;
            int c  = d / 9;
            int r  = d - c * 9;
            int kh = r / 3, kw = r - kh * 3;
            int n  = n0 + nl;
            int bi = n >> 12;
            int s  = n & 4095;
            int ho = s >> 6, wo = s & 63;
            int h = ho + kh - 1, w = wo + kw - 1;
            float v = 0.0f;
            if ((unsigned)h < (unsigned)HW && (unsigned)w < (unsigned)HW)
                v = x[(((size_t)bi * 64 + c) * HW + h) * HW + w];
            float a9[9];
            compute_acts(v, a9);
#pragma unroll
            for (int k = 0; k < 9; ++k)
                sT[nl][dl * 9 + k] = __float2half_rn(a9[k]);
        }
        __syncthreads();
        uint32_t* gA32 = (uint32_t*)g_A;
#pragma unroll
        for (int j = 0; j < (ACT_TN * (ACT_DC * 9 / 2)) / 256; ++j) {
            int idx = tid + j * 256;
            int rown = idx / 288;
            int col  = idx - rown * 288;
            gA32[(size_t)(n0 + rown) * (NK / 2) + (d0 * 9) / 2 + col] =
                *(const uint32_t*)&sT[rown][col * 2];
        }
        __syncthreads();
    }
}

// ---------------------------------------------------------------------------
// Kernel 2: combined weights -> g_Wb[oc][k] fp16
// ---------------------------------------------------------------------------
__global__ void kan_wcomb_kernel(const float* __restrict__ bw,
                                 const float* __restrict__ sw,
                                 const float* __restrict__ ss) {
    int idx = blockIdx.x * blockDim.x + threadIdx.x;
    if (idx >= OC * NK) return;
    int oc  = idx / NK;
    int rem = idx - oc * NK;
    int d   = rem / 9;
    int kc  = rem - d * 9;
    float v;
    if (kc == 0) v = bw[oc * D_TOT + d];
    else         v = sw[(oc * D_TOT + d) * NBAS + (kc - 1)] * ss[oc * D_TOT + d];
    g_Wb[idx] = __float2half_rn(v);
}

// ---------------------------------------------------------------------------
// Kernel 3: HMMA GEMM. grid = 128 M-tiles; CTA: M=128, N=128(all OC).
// 8 warps: 2 (M) x 4 (N); warp tile 64x32 = 4x4 m16n8k16 frags.
// Double-buffered SMEM tiles (SW128), cp.async prefetch.
// ---------------------------------------------------------------------------
#define GT 256
#define TILE_BYTES 16384   // 128 rows x 128 B

__global__ __launch_bounds__(GT, 1)
void kan_gemm_kernel(float* __restrict__ out) {
    extern __shared__ char dynsmem[];
    const int tid  = threadIdx.x;
    const int lane = tid & 31;
    const int wid  = tid >> 5;
    const int wm   = wid & 1;    // 0..1 -> M offset 0/64
    const int wn   = wid >> 1;   // 0..3 -> N offset 0/32/64/96
    const int mtile = blockIdx.x;

    uint32_t raw = smem_u32(dynsmem);
    uint32_t smadr = (raw + 1023) & ~1023u;

    const uint32_t aBuf[2] = {smadr,             smadr + TILE_BYTES};
    const uint32_t wBuf[2] = {smadr + 2*TILE_BYTES, smadr + 3*TILE_BYTES};

    const __half* Abase = g_A + (size_t)mtile * 128 * NK;
    const __half* Wbase = g_Wb;

    // per-thread cp.async mapping: 4 x 16B per tile
    int goff[4], swoff[4];
#pragma unroll
    for (int it = 0; it < 4; ++it) {
        int idx = tid + it * GT;
        int row = idx >> 3;
        int cc  = idx & 7;
        goff[it]  = row * NK + cc * 8;            // in halves
        swoff[it] = SW128(row * 128 + cc * 16);   // bytes within tile
    }

    float acc[4][4][4];
#pragma unroll
    for (int i = 0; i < 4; ++i)
#pragma unroll
        for (int j = 0; j < 4; ++j)
#pragma unroll
            for (int k = 0; k < 4; ++k) acc[i][j][k] = 0.0f;

    // ldmatrix per-lane row/col pieces
    const int lr  = lane & 15;          // row within 16-row frag
    const int lcb = (lane >> 4) * 16;   // 0 or 16 bytes (k halves 0-7 / 8-15)

    // prefetch chunk 0
#pragma unroll
    for (int it = 0; it < 4; ++it) {
        CP_ASYNC16(aBuf[0] + swoff[it], Abase + goff[it]);
        CP_ASYNC16(wBuf[0] + swoff[it], Wbase + goff[it]);
    }
    CP_COMMIT();

    for (int i = 0; i < NCHUNK; ++i) {
        CP_WAIT0();
        __syncthreads();
        if (i + 1 < NCHUNK) {
            const int b2 = (i + 1) & 1;
            const int k0 = (i + 1) * KC;
#pragma unroll
            for (int it = 0; it < 4; ++it) {
                CP_ASYNC16(aBuf[b2] + swoff[it], Abase + goff[it] + k0);
                CP_ASYNC16(wBuf[b2] + swoff[it], Wbase + goff[it] + k0);
            }
            CP_COMMIT();
        }
        const int b = i & 1;
        const uint32_t aB = aBuf[b], wB = wBuf[b];
#pragma unroll
        for (int ks = 0; ks < 4; ++ks) {
            const int colb = ks * 32 + lcb;
            uint32_t af[4][4];
#pragma unroll
            for (int am = 0; am < 4; ++am) {
                int row = wm * 64 + am * 16 + lr;
                ldsm_x4(af[am], aB + SW128(row * 128 + colb));
            }
            uint32_t bf[2][4];
#pragma unroll
            for (int bp = 0; bp < 2; ++bp) {
                int row = wn * 32 + bp * 16 + lr;
                ldsm_x4(bf[bp], wB + SW128(row * 128 + colb));
            }
#pragma unroll
            for (int am = 0; am < 4; ++am)
#pragma unroll
                for (int bn = 0; bn < 4; ++bn) {
                    const int bp = bn >> 1, j = bn & 1;
                    mma16816(acc[am][bn], af[am], bf[bp][j], bf[bp][j + 2]);
                }
        }
    }

    __syncthreads();   // done with tile buffers; reuse smem for epilogue

    // stage C to smem: sepi[m][oc], stride 130 floats (even -> float2 ok)
    float* sepi = (float*)(uintptr_t)(dynsmem + (smadr - raw));
#pragma unroll
    for (int am = 0; am < 4; ++am)
#pragma unroll
        for (int bn = 0; bn < 4; ++bn) {
            int m = wm * 64 + am * 16 + (lane >> 2);
            int n = wn * 32 + bn * 8 + (lane & 3) * 2;
            *(float2*)&sepi[m * 130 + n]       = make_float2(acc[am][bn][0], acc[am][bn][1]);
            *(float2*)&sepi[(m + 8) * 130 + n] = make_float2(acc[am][bn][2], acc[am][bn][3]);
        }
    __syncthreads();

    // coalesced global write: out[(bi*OC+oc)*4096 + s], s = mtile*128 + i
    const int bi = mtile >> 5;
    const int s_base = (mtile * 128) & 4095;
    float* outb = out + ((size_t)bi * OC << 12);
#pragma unroll
    for (int j = 0; j < (128 * OC) / (GT * 4); ++j) {
        int idx = tid + j * GT;            // 0..4095 (float4 units)
        int oc = idx >> 5;
        int i0 = (idx & 31) * 4;
        float4 v;
        v.x = sepi[(i0 + 0) * 130 + oc];
        v.y = sepi[(i0 + 1) * 130 + oc];
        v.z = sepi[(i0 + 2) * 130 + oc];
        v.w = sepi[(i0 + 3) * 130 + oc];
        *(float4*)&outb[((size_t)oc << 12) + s_base + i0] = v;
    }
}

// ---------------------------------------------------------------------------
extern "C" void kernel_launch(void* const* d_in, const int* in_sizes, int n_in,
                              void* d_out, int out_size) {
    const float* x  = (const float*)d_in[0];
    const float* bw = (const float*)d_in[1];
    const float* sw = (const float*)d_in[2];
    const float* ss = (const float*)d_in[3];
    float* out = (float*)d_out;

    static const int GEMM_SMEM = 1024 + 128 * 130 * 4;   // 67584 >= max(tiles, epi)
    cudaFuncSetAttribute(kan_gemm_kernel,
                         cudaFuncAttributeMaxDynamicSharedMemorySize, GEMM_SMEM);

    kan_wcomb_kernel<<<(OC * NK + 255) / 256, 256>>>(bw, sw, ss);
    kan_act_kernel<<<NROWS / ACT_TN, 256>>>(x);
    kan_gemm_kernel<<<NROWS / 128, GT, GEMM_SMEM>>>(out);
}